// round 2
// baseline (speedup 1.0000x reference)
#include <cuda_runtime.h>

// ---------------------------------------------------------------------------
// HydraAttention: B=8, L=4096, dim=1024, n_heads=8, d_head=128, d=16
//  Q = x@Wq^T+bq ; K,V same      (GEMM  M=32768, N=128 x3, K=1024)
//  qn = Q/||Q||_d ; kn = K/||K||_d      (per-head 16-dim norms)
//  kv[b,h,:] = sum_L kn*V
//  out = LayerNorm_d(qn * kv) * gamma + beta
// ---------------------------------------------------------------------------

static constexpr int Bb  = 8;
static constexpr int Ll  = 4096;
static constexpr int DIM = 1024;
static constexpr int DH  = 128;
static constexpr int NH  = 8;
static constexpr int Dd  = 16;
static constexpr int MTOK = Bb * Ll;      // 32768

// Scratch (static device globals -- no allocations allowed)
__device__ float g_qkv[3][MTOK * DH];     // 48 MB: Q, K, V in [token, 128] layout
__device__ float g_kvpart[Bb * NH][4][Dd];

// ---------------- packed f32x2 helpers (Blackwell) -------------------------
__device__ __forceinline__ unsigned long long pack2(float lo, float hi) {
    unsigned long long r;
    asm("mov.b64 %0, {%1, %2};" : "=l"(r) : "f"(lo), "f"(hi));
    return r;
}
__device__ __forceinline__ void ffma2(unsigned long long& d,
                                      unsigned long long a,
                                      unsigned long long b) {
    asm("fma.rn.f32x2 %0, %1, %2, %0;" : "+l"(d) : "l"(a), "l"(b));
}
__device__ __forceinline__ void unpack2(unsigned long long v, float& lo, float& hi) {
    asm("mov.b64 {%0, %1}, %2;" : "=f"(lo), "=f"(hi) : "l"(v));
}

// ---------------- Kernel 1: fused QKV GEMM ---------------------------------
// grid = (3, 256): blockIdx.x selects {Q,K,V}, blockIdx.y = M tile (128 rows)
// BM=128, BN=128(=full N), BK=16, 256 threads, 8x8 per thread via f32x2 pairs
#define BKT 16
#define BMP 132   // padded stride (mult of 4 for float4-aligned rows)

__global__ __launch_bounds__(256) void qkv_gemm(
    const float* __restrict__ X,
    const float* __restrict__ Wq, const float* __restrict__ bq,
    const float* __restrict__ Wk, const float* __restrict__ bk,
    const float* __restrict__ Wv, const float* __restrict__ bv)
{
    const int mat = blockIdx.x;
    const float* __restrict__ W    = (mat == 0) ? Wq : (mat == 1) ? Wk : Wv;
    const float* __restrict__ bias = (mat == 0) ? bq : (mat == 1) ? bk : bv;
    float* __restrict__ C = g_qkv[mat];

    __shared__ __align__(16) float As[2][BKT][BMP];
    __shared__ __align__(16) float Bs[2][BKT][BMP];

    const int tid = threadIdx.x;
    const int tx  = tid & 15;    // n direction
    const int ty  = tid >> 4;    // m direction
    const int bm  = blockIdx.y * 128;

    // tile-load mapping: 512 float4 per operand tile, 2 per thread
    const int lrow = tid >> 2;          // 0..63 (also +64)
    const int lcol = (tid & 3) * 4;     // 0,4,8,12

    const float* Xg = X + (size_t)(bm + lrow) * DIM + lcol;
    const float* Wg = W + (size_t)lrow * DIM + lcol;

    unsigned long long acc[8][4];
#pragma unroll
    for (int i = 0; i < 8; i++)
#pragma unroll
        for (int j = 0; j < 4; j++) acc[i][j] = 0ULL;

    // preload tile 0
    float4 xa = *(const float4*)(Xg);
    float4 xb = *(const float4*)(Xg + 64 * DIM);
    float4 wa = *(const float4*)(Wg);
    float4 wb = *(const float4*)(Wg + 64 * DIM);
    {
        As[0][lcol+0][lrow] = xa.x; As[0][lcol+1][lrow] = xa.y;
        As[0][lcol+2][lrow] = xa.z; As[0][lcol+3][lrow] = xa.w;
        As[0][lcol+0][lrow+64] = xb.x; As[0][lcol+1][lrow+64] = xb.y;
        As[0][lcol+2][lrow+64] = xb.z; As[0][lcol+3][lrow+64] = xb.w;
        Bs[0][lcol+0][lrow] = wa.x; Bs[0][lcol+1][lrow] = wa.y;
        Bs[0][lcol+2][lrow] = wa.z; Bs[0][lcol+3][lrow] = wa.w;
        Bs[0][lcol+0][lrow+64] = wb.x; Bs[0][lcol+1][lrow+64] = wb.y;
        Bs[0][lcol+2][lrow+64] = wb.z; Bs[0][lcol+3][lrow+64] = wb.w;
    }
    __syncthreads();

    const int NT = DIM / BKT;   // 64
    int buf = 0;
    for (int t = 0; t < NT; t++) {
        // prefetch next tile into registers
        if (t + 1 < NT) {
            const float* xp = Xg + (t + 1) * BKT;
            const float* wp = Wg + (t + 1) * BKT;
            xa = *(const float4*)(xp);
            xb = *(const float4*)(xp + 64 * DIM);
            wa = *(const float4*)(wp);
            wb = *(const float4*)(wp + 64 * DIM);
        }

#pragma unroll
        for (int kk = 0; kk < BKT; kk++) {
            float4 a0 = *(const float4*)&As[buf][kk][ty * 4];
            float4 a1 = *(const float4*)&As[buf][kk][64 + ty * 4];
            ulonglong2 b0 = *(const ulonglong2*)&Bs[buf][kk][tx * 4];
            ulonglong2 b1 = *(const ulonglong2*)&Bs[buf][kk][64 + tx * 4];
            unsigned long long ap[8];
            ap[0] = pack2(a0.x, a0.x); ap[1] = pack2(a0.y, a0.y);
            ap[2] = pack2(a0.z, a0.z); ap[3] = pack2(a0.w, a0.w);
            ap[4] = pack2(a1.x, a1.x); ap[5] = pack2(a1.y, a1.y);
            ap[6] = pack2(a1.z, a1.z); ap[7] = pack2(a1.w, a1.w);
#pragma unroll
            for (int i = 0; i < 8; i++) {
                ffma2(acc[i][0], ap[i], b0.x);
                ffma2(acc[i][1], ap[i], b0.y);
                ffma2(acc[i][2], ap[i], b1.x);
                ffma2(acc[i][3], ap[i], b1.y);
            }
        }

        if (t + 1 < NT) {
            int nb = buf ^ 1;
            As[nb][lcol+0][lrow] = xa.x; As[nb][lcol+1][lrow] = xa.y;
            As[nb][lcol+2][lrow] = xa.z; As[nb][lcol+3][lrow] = xa.w;
            As[nb][lcol+0][lrow+64] = xb.x; As[nb][lcol+1][lrow+64] = xb.y;
            As[nb][lcol+2][lrow+64] = xb.z; As[nb][lcol+3][lrow+64] = xb.w;
            Bs[nb][lcol+0][lrow] = wa.x; Bs[nb][lcol+1][lrow] = wa.y;
            Bs[nb][lcol+2][lrow] = wa.z; Bs[nb][lcol+3][lrow] = wa.w;
            Bs[nb][lcol+0][lrow+64] = wb.x; Bs[nb][lcol+1][lrow+64] = wb.y;
            Bs[nb][lcol+2][lrow+64] = wb.z; Bs[nb][lcol+3][lrow+64] = wb.w;
        }
        __syncthreads();
        buf ^= 1;
    }

    // epilogue: unpack, add bias, store
    const float4 bi0 = *(const float4*)&bias[tx * 4];
    const float4 bi1 = *(const float4*)&bias[64 + tx * 4];
#pragma unroll
    for (int i = 0; i < 8; i++) {
        const int m = (i < 4) ? (ty * 4 + i) : (64 + ty * 4 + (i - 4));
        float4 o0, o1;
        unpack2(acc[i][0], o0.x, o0.y);
        unpack2(acc[i][1], o0.z, o0.w);
        unpack2(acc[i][2], o1.x, o1.y);
        unpack2(acc[i][3], o1.z, o1.w);
        o0.x += bi0.x; o0.y += bi0.y; o0.z += bi0.z; o0.w += bi0.w;
        o1.x += bi1.x; o1.y += bi1.y; o1.z += bi1.z; o1.w += bi1.w;
        float* cp = C + (size_t)(bm + m) * DH;
        *(float4*)&cp[tx * 4]      = o0;
        *(float4*)&cp[64 + tx * 4] = o1;
    }
}

// ---------------- Kernel 2: kv partial reduction ---------------------------
// grid = (64, 4): one (b,h) per blockIdx.x, L split in 4 chunks of 1024
__global__ __launch_bounds__(256) void kv_reduce()
{
    const int bh    = blockIdx.x;     // 0..63
    const int chunk = blockIdx.y;     // 0..3
    const int b = bh >> 3, h = bh & 7;
    const float* __restrict__ K = g_qkv[1];
    const float* __restrict__ V = g_qkv[2];

    float acc[Dd];
#pragma unroll
    for (int d = 0; d < Dd; d++) acc[d] = 0.f;

    for (int l = chunk * 1024 + threadIdx.x; l < (chunk + 1) * 1024; l += 256) {
        const size_t base = (size_t)(b * Ll + l) * DH + h * Dd;
        float kx[Dd], vx[Dd];
        const float4* kp = (const float4*)(K + base);
        const float4* vp = (const float4*)(V + base);
#pragma unroll
        for (int q = 0; q < 4; q++) {
            float4 kv4 = kp[q];
            kx[q*4+0] = kv4.x; kx[q*4+1] = kv4.y; kx[q*4+2] = kv4.z; kx[q*4+3] = kv4.w;
            float4 vv4 = vp[q];
            vx[q*4+0] = vv4.x; vx[q*4+1] = vv4.y; vx[q*4+2] = vv4.z; vx[q*4+3] = vv4.w;
        }
        float ss = 0.f;
#pragma unroll
        for (int d = 0; d < Dd; d++) ss += kx[d] * kx[d];
        const float rn = rsqrtf(ss);
#pragma unroll
        for (int d = 0; d < Dd; d++) acc[d] += kx[d] * rn * vx[d];
    }

    __shared__ float red[256][17];   // pad to kill bank conflicts
#pragma unroll
    for (int d = 0; d < Dd; d++) red[threadIdx.x][d] = acc[d];
    __syncthreads();
    for (int s = 128; s > 0; s >>= 1) {
        if (threadIdx.x < s) {
#pragma unroll
            for (int d = 0; d < Dd; d++)
                red[threadIdx.x][d] += red[threadIdx.x + s][d];
        }
        __syncthreads();
    }
    if (threadIdx.x < Dd)
        g_kvpart[bh][chunk][threadIdx.x] = red[0][threadIdx.x];
}

// ---------------- Kernel 3: q-normalize * kv, LayerNorm --------------------
// one thread per output row; idx = b*32768 + h*4096 + l -> out stores coalesced
__global__ __launch_bounds__(256) void finalize(
    const float* __restrict__ gamma, const float* __restrict__ beta,
    float* __restrict__ out)
{
    const int idx = blockIdx.x * blockDim.x + threadIdx.x;   // 0..262143
    const int l = idx & (Ll - 1);
    const int h = (idx >> 12) & 7;
    const int b = idx >> 15;

    const size_t qbase = (size_t)(b * Ll + l) * DH + h * Dd;
    float q[Dd];
    const float4* qp = (const float4*)(g_qkv[0] + qbase);
#pragma unroll
    for (int g = 0; g < 4; g++) {
        float4 v = qp[g];
        q[g*4+0] = v.x; q[g*4+1] = v.y; q[g*4+2] = v.z; q[g*4+3] = v.w;
    }

    const int bh = (b << 3) | h;
    float kv[Dd];
#pragma unroll
    for (int d = 0; d < Dd; d++)
        kv[d] = g_kvpart[bh][0][d] + g_kvpart[bh][1][d]
              + g_kvpart[bh][2][d] + g_kvpart[bh][3][d];

    float ss = 0.f;
#pragma unroll
    for (int d = 0; d < Dd; d++) ss += q[d] * q[d];
    const float rn = rsqrtf(ss);

    float a[Dd];
    float mu = 0.f;
#pragma unroll
    for (int d = 0; d < Dd; d++) { a[d] = q[d] * rn * kv[d]; mu += a[d]; }
    mu *= (1.f / Dd);
    float var = 0.f;
#pragma unroll
    for (int d = 0; d < Dd; d++) { float t = a[d] - mu; var += t * t; }
    var *= (1.f / Dd);
    const float rs = rsqrtf(var + 1e-5f);

    float* op = out + (size_t)idx * Dd;
#pragma unroll
    for (int g = 0; g < 4; g++) {
        float4 o;
        o.x = (a[g*4+0] - mu) * rs * gamma[g*4+0] + beta[g*4+0];
        o.y = (a[g*4+1] - mu) * rs * gamma[g*4+1] + beta[g*4+1];
        o.z = (a[g*4+2] - mu) * rs * gamma[g*4+2] + beta[g*4+2];
        o.w = (a[g*4+3] - mu) * rs * gamma[g*4+3] + beta[g*4+3];
        *(float4*)&op[g * 4] = o;
    }
}

// ---------------------------------------------------------------------------
extern "C" void kernel_launch(void* const* d_in, const int* in_sizes, int n_in,
                              void* d_out, int out_size)
{
    (void)in_sizes; (void)n_in; (void)out_size;
    const float* x     = (const float*)d_in[0];
    const float* Wq    = (const float*)d_in[1];
    const float* bq    = (const float*)d_in[2];
    const float* Wk    = (const float*)d_in[3];
    const float* bk    = (const float*)d_in[4];
    const float* Wv    = (const float*)d_in[5];
    const float* bv    = (const float*)d_in[6];
    const float* gamma = (const float*)d_in[7];
    const float* beta  = (const float*)d_in[8];
    float* out = (float*)d_out;

    qkv_gemm<<<dim3(3, MTOK / 128), 256>>>(x, Wq, bq, Wk, bk, Wv, bv);
    kv_reduce<<<dim3(Bb * NH, 4), 256>>>();
    finalize<<<(Bb * NH * Ll) / 256, 256>>>(gamma, beta, out);
}

// round 4
// speedup vs baseline: 1.8242x; 1.8242x over previous
#include <cuda_runtime.h>
#include <cuda_bf16.h>
#include <cstdint>

// ---------------------------------------------------------------------------
// HydraAttention: B=8, L=4096, dim=1024, n_heads=8, d_head=128, d=16
// Round 4: mma.sync bf16 3-term split GEMM (sm_100-base-safe, no tcgen05)
// ---------------------------------------------------------------------------

static constexpr int Bb  = 8;
static constexpr int Ll  = 4096;
static constexpr int DIM = 1024;
static constexpr int DH  = 128;
static constexpr int NH  = 8;
static constexpr int Dd  = 16;
static constexpr int MTOK = Bb * Ll;      // 32768

// Scratch (static device globals -- no allocations allowed)
__device__ float g_qkv[3][MTOK * DH];                         // 48 MB
__device__ float g_kvpart[Bb * NH][4][Dd];
__device__ __align__(16) __nv_bfloat16 g_xhi[(size_t)MTOK * DIM];  // 64 MB
__device__ __align__(16) __nv_bfloat16 g_xlo[(size_t)MTOK * DIM];  // 64 MB
__device__ __align__(16) __nv_bfloat16 g_whi[3 * DH * DIM];
__device__ __align__(16) __nv_bfloat16 g_wlo[3 * DH * DIM];

// ---------------- PTX helpers ----------------------------------------------
__device__ __forceinline__ uint32_t smem_u32(const void* p) {
    uint32_t a;
    asm("{ .reg .u64 t; cvta.to.shared.u64 t, %1; cvt.u32.u64 %0, t; }"
        : "=r"(a) : "l"(p));
    return a;
}
__device__ __forceinline__ void cpasync16(uint32_t dst, const void* src) {
    asm volatile("cp.async.cg.shared.global [%0], [%1], 16;" :: "r"(dst), "l"(src));
}
__device__ __forceinline__ void ldsm4(uint32_t* r, uint32_t a) {
    asm volatile("ldmatrix.sync.aligned.m8n8.x4.shared.b16 {%0,%1,%2,%3}, [%4];"
        : "=r"(r[0]), "=r"(r[1]), "=r"(r[2]), "=r"(r[3]) : "r"(a));
}
__device__ __forceinline__ void mma_bf16(float* c, const uint32_t* a, const uint32_t* b) {
    asm volatile(
        "mma.sync.aligned.m16n8k16.row.col.f32.bf16.bf16.f32 "
        "{%0,%1,%2,%3}, {%4,%5,%6,%7}, {%8,%9}, {%0,%1,%2,%3};"
        : "+f"(c[0]), "+f"(c[1]), "+f"(c[2]), "+f"(c[3])
        : "r"(a[0]), "r"(a[1]), "r"(a[2]), "r"(a[3]), "r"(b[0]), "r"(b[1]));
}

// ---------------- Kernel 0a: split X -> bf16 hi/lo (row-major) -------------
__global__ __launch_bounds__(256) void split_x(const float* __restrict__ X) {
    const size_t t = (size_t)blockIdx.x * 256 + threadIdx.x;   // 8 elems each
    const float4* p = (const float4*)(X + t * 8);
    float4 a = p[0], b = p[1];
    float xs[8] = {a.x, a.y, a.z, a.w, b.x, b.y, b.z, b.w};
    __align__(16) __nv_bfloat16 hi[8];
    __align__(16) __nv_bfloat16 lo[8];
#pragma unroll
    for (int i = 0; i < 8; i++) {
        hi[i] = __float2bfloat16(xs[i]);
        lo[i] = __float2bfloat16(xs[i] - __bfloat162float(hi[i]));
    }
    *(uint4*)(g_xhi + t * 8) = *(const uint4*)hi;
    *(uint4*)(g_xlo + t * 8) = *(const uint4*)lo;
}

// ---------------- Kernel 0b: split weights ---------------------------------
__global__ __launch_bounds__(256) void split_w(const float* __restrict__ Wq,
                                               const float* __restrict__ Wk,
                                               const float* __restrict__ Wv) {
    const size_t t = (size_t)blockIdx.x * 256 + threadIdx.x;
    const size_t e = t * 8;                      // element offset, 0..393215
    const int mat = (int)(e >> 17);              // 131072 elems per matrix
    const size_t off = e & 131071;
    const float* W = (mat == 0) ? Wq : (mat == 1) ? Wk : Wv;
    const float4* p = (const float4*)(W + off);
    float4 a = p[0], b = p[1];
    float xs[8] = {a.x, a.y, a.z, a.w, b.x, b.y, b.z, b.w};
    __align__(16) __nv_bfloat16 hi[8];
    __align__(16) __nv_bfloat16 lo[8];
#pragma unroll
    for (int i = 0; i < 8; i++) {
        hi[i] = __float2bfloat16(xs[i]);
        lo[i] = __float2bfloat16(xs[i] - __bfloat162float(hi[i]));
    }
    *(uint4*)(g_whi + e) = *(const uint4*)hi;
    *(uint4*)(g_wlo + e) = *(const uint4*)lo;
}

// ---------------- Kernel 1: mma.sync QKV GEMM ------------------------------
// grid = (3, 256): mat x 128-row M block. BN=128, BK=64.
// smem per stage 64KB: Ah(16K) Al(16K) Bh(16K) Bl(16K), 2 stages = 128KB.
// 8 warps 4x2 (MxN), warp tile 32x64, HMMA m16n8k16 bf16.
static constexpr uint32_t STAGE = 65536;
static constexpr uint32_t GEMM_SMEM = 2 * STAGE;

__global__ __launch_bounds__(256) void qkv_gemm_mma(
    const float* __restrict__ bq, const float* __restrict__ bk,
    const float* __restrict__ bv)
{
    extern __shared__ __align__(128) unsigned char smem[];
    const uint32_t sbase = smem_u32(smem);
    const int tid = threadIdx.x, lid = tid & 31, wid = tid >> 5;
    const int mat = blockIdx.x;
    const int bm  = blockIdx.y * 128;
    const int wrow = (wid >> 1) * 32;     // warp M offset
    const int wcol = (wid & 1) * 64;      // warp N offset

    float acc[2][8][4];
#pragma unroll
    for (int i = 0; i < 2; i++)
#pragma unroll
        for (int j = 0; j < 8; j++)
#pragma unroll
            for (int k = 0; k < 4; k++) acc[i][j][k] = 0.f;

    auto load_stage = [&](int kc, int s) {
#pragma unroll
        for (int i = 0; i < 4; i++) {
            const int id  = tid + 256 * i;          // 0..1023
            const int row = id >> 3;                // 0..127
            const int c16 = id & 7;                 // 16B chunk in 128B row
            const uint32_t doff = sbase + (uint32_t)s * STAGE
                                + row * 128 + ((c16 ^ (row & 7)) << 4);
            const size_t gA = (size_t)(bm + row) * DIM + kc * 64 + c16 * 8;
            const size_t gB = (size_t)(mat * DH + row) * DIM + kc * 64 + c16 * 8;
            cpasync16(doff,         g_xhi + gA);
            cpasync16(doff + 16384, g_xlo + gA);
            cpasync16(doff + 32768, g_whi + gB);
            cpasync16(doff + 49152, g_wlo + gB);
        }
        asm volatile("cp.async.commit_group;" ::: "memory");
    };

    load_stage(0, 0);
    load_stage(1, 1);

    for (int c = 0; c < 16; c++) {
        const int s = c & 1;
        asm volatile("cp.async.wait_group 1;" ::: "memory");
        __syncthreads();
        const uint32_t st = sbase + (uint32_t)s * STAGE;

#pragma unroll
        for (int ks = 0; ks < 4; ks++) {
            uint32_t ah[8], al[8], bb[16];
            // A fragments (hi & lo): 2 m16 tiles
#pragma unroll
            for (int mt = 0; mt < 2; mt++) {
                const int row = wrow + mt * 16 + (lid & 15);
                const int c16 = ks * 2 + (lid >> 4);
                const uint32_t off = st + row * 128 + ((c16 ^ (row & 7)) << 4);
                ldsm4(ah + mt * 4, off);
                ldsm4(al + mt * 4, off + 16384);
            }
            // Bh fragments: 4 x4-ldmatrix cover 8 n8 tiles
#pragma unroll
            for (int np = 0; np < 4; np++) {
                const int row = wcol + np * 16 + (lid & 7) + ((lid >> 4) << 3);
                const int c16 = ks * 2 + ((lid >> 3) & 1);
                const uint32_t off = st + 32768 + row * 128 + ((c16 ^ (row & 7)) << 4);
                ldsm4(bb + np * 4, off);
            }
            // Ah*Bh + Al*Bh
#pragma unroll
            for (int mt = 0; mt < 2; mt++)
#pragma unroll
                for (int np = 0; np < 4; np++) {
                    mma_bf16(acc[mt][np*2],     ah + mt*4, bb + np*4);
                    mma_bf16(acc[mt][np*2 + 1], ah + mt*4, bb + np*4 + 2);
                    mma_bf16(acc[mt][np*2],     al + mt*4, bb + np*4);
                    mma_bf16(acc[mt][np*2 + 1], al + mt*4, bb + np*4 + 2);
                }
            // Bl fragments (overwrite bb)
#pragma unroll
            for (int np = 0; np < 4; np++) {
                const int row = wcol + np * 16 + (lid & 7) + ((lid >> 4) << 3);
                const int c16 = ks * 2 + ((lid >> 3) & 1);
                const uint32_t off = st + 49152 + row * 128 + ((c16 ^ (row & 7)) << 4);
                ldsm4(bb + np * 4, off);
            }
            // Ah*Bl
#pragma unroll
            for (int mt = 0; mt < 2; mt++)
#pragma unroll
                for (int np = 0; np < 4; np++) {
                    mma_bf16(acc[mt][np*2],     ah + mt*4, bb + np*4);
                    mma_bf16(acc[mt][np*2 + 1], ah + mt*4, bb + np*4 + 2);
                }
        }
        __syncthreads();
        if (c + 2 < 16) load_stage(c + 2, s);
    }

    // epilogue: add bias, store fp32
    const float* bias = (mat == 0) ? bq : (mat == 1) ? bk : bv;
    float* __restrict__ Cp = g_qkv[mat];
    const int tr = lid >> 2, tc = (lid & 3) * 2;
#pragma unroll
    for (int mt = 0; mt < 2; mt++)
#pragma unroll
        for (int n8 = 0; n8 < 8; n8++) {
            const int col = wcol + n8 * 8 + tc;
            const float b0 = bias[col], b1 = bias[col + 1];
            const int r0 = bm + wrow + mt * 16 + tr;
            float2 v0 = {acc[mt][n8][0] + b0, acc[mt][n8][1] + b1};
            float2 v1 = {acc[mt][n8][2] + b0, acc[mt][n8][3] + b1};
            *(float2*)&Cp[(size_t)r0 * DH + col]       = v0;
            *(float2*)&Cp[(size_t)(r0 + 8) * DH + col] = v1;
        }
}

// ---------------- Kernel 2: kv partial reduction ---------------------------
__global__ __launch_bounds__(256) void kv_reduce() {
    const int bh    = blockIdx.x;
    const int chunk = blockIdx.y;
    const int b = bh >> 3, h = bh & 7;
    const float* __restrict__ K = g_qkv[1];
    const float* __restrict__ V = g_qkv[2];

    float acc[Dd];
#pragma unroll
    for (int d = 0; d < Dd; d++) acc[d] = 0.f;

    for (int l = chunk * 1024 + threadIdx.x; l < (chunk + 1) * 1024; l += 256) {
        const size_t base = (size_t)(b * Ll + l) * DH + h * Dd;
        float kx[Dd], vx[Dd];
        const float4* kp = (const float4*)(K + base);
        const float4* vp = (const float4*)(V + base);
#pragma unroll
        for (int q = 0; q < 4; q++) {
            float4 kv4 = kp[q];
            kx[q*4+0] = kv4.x; kx[q*4+1] = kv4.y; kx[q*4+2] = kv4.z; kx[q*4+3] = kv4.w;
            float4 vv4 = vp[q];
            vx[q*4+0] = vv4.x; vx[q*4+1] = vv4.y; vx[q*4+2] = vv4.z; vx[q*4+3] = vv4.w;
        }
        float ss = 0.f;
#pragma unroll
        for (int d = 0; d < Dd; d++) ss += kx[d] * kx[d];
        const float rn = rsqrtf(ss);
#pragma unroll
        for (int d = 0; d < Dd; d++) acc[d] += kx[d] * rn * vx[d];
    }

    __shared__ float red[256][17];
#pragma unroll
    for (int d = 0; d < Dd; d++) red[threadIdx.x][d] = acc[d];
    __syncthreads();
    for (int s = 128; s > 0; s >>= 1) {
        if (threadIdx.x < s) {
#pragma unroll
            for (int d = 0; d < Dd; d++)
                red[threadIdx.x][d] += red[threadIdx.x + s][d];
        }
        __syncthreads();
    }
    if (threadIdx.x < Dd)
        g_kvpart[bh][chunk][threadIdx.x] = red[0][threadIdx.x];
}

// ---------------- Kernel 3: q-normalize * kv, LayerNorm --------------------
__global__ __launch_bounds__(256) void finalize(
    const float* __restrict__ gamma, const float* __restrict__ beta,
    float* __restrict__ out)
{
    const int idx = blockIdx.x * blockDim.x + threadIdx.x;
    const int l = idx & (Ll - 1);
    const int h = (idx >> 12) & 7;
    const int b = idx >> 15;

    const size_t qbase = (size_t)(b * Ll + l) * DH + h * Dd;
    float q[Dd];
    const float4* qp = (const float4*)(g_qkv[0] + qbase);
#pragma unroll
    for (int g = 0; g < 4; g++) {
        float4 v = qp[g];
        q[g*4+0] = v.x; q[g*4+1] = v.y; q[g*4+2] = v.z; q[g*4+3] = v.w;
    }

    const int bh = (b << 3) | h;
    float kv[Dd];
#pragma unroll
    for (int d = 0; d < Dd; d++)
        kv[d] = g_kvpart[bh][0][d] + g_kvpart[bh][1][d]
              + g_kvpart[bh][2][d] + g_kvpart[bh][3][d];

    float ss = 0.f;
#pragma unroll
    for (int d = 0; d < Dd; d++) ss += q[d] * q[d];
    const float rn = rsqrtf(ss);

    float a[Dd];
    float mu = 0.f;
#pragma unroll
    for (int d = 0; d < Dd; d++) { a[d] = q[d] * rn * kv[d]; mu += a[d]; }
    mu *= (1.f / Dd);
    float var = 0.f;
#pragma unroll
    for (int d = 0; d < Dd; d++) { float t = a[d] - mu; var += t * t; }
    var *= (1.f / Dd);
    const float rs = rsqrtf(var + 1e-5f);

    float* op = out + (size_t)idx * Dd;
#pragma unroll
    for (int g = 0; g < 4; g++) {
        float4 o;
        o.x = (a[g*4+0] - mu) * rs * gamma[g*4+0] + beta[g*4+0];
        o.y = (a[g*4+1] - mu) * rs * gamma[g*4+1] + beta[g*4+1];
        o.z = (a[g*4+2] - mu) * rs * gamma[g*4+2] + beta[g*4+2];
        o.w = (a[g*4+3] - mu) * rs * gamma[g*4+3] + beta[g*4+3];
        *(float4*)&op[g * 4] = o;
    }
}

// ---------------------------------------------------------------------------
extern "C" void kernel_launch(void* const* d_in, const int* in_sizes, int n_in,
                              void* d_out, int out_size)
{
    (void)in_sizes; (void)n_in; (void)out_size;
    const float* x     = (const float*)d_in[0];
    const float* Wq    = (const float*)d_in[1];
    const float* bq    = (const float*)d_in[2];
    const float* Wk    = (const float*)d_in[3];
    const float* bk    = (const float*)d_in[4];
    const float* Wv    = (const float*)d_in[5];
    const float* bv    = (const float*)d_in[6];
    const float* gamma = (const float*)d_in[7];
    const float* beta  = (const float*)d_in[8];
    float* out = (float*)d_out;

    static bool attr_set = false;
    if (!attr_set) {
        cudaFuncSetAttribute(qkv_gemm_mma,
                             cudaFuncAttributeMaxDynamicSharedMemorySize, GEMM_SMEM);
        attr_set = true;
    }

    split_x<<<16384, 256>>>(x);
    split_w<<<192, 256>>>(Wq, Wk, Wv);
    qkv_gemm_mma<<<dim3(3, 256), 256, GEMM_SMEM>>>(bq, bk, bv);
    kv_reduce<<<dim3(Bb * NH, 4), 256>>>();
    finalize<<<(Bb * NH * Ll) / 256, 256>>>(gamma, beta, out);
}